// round 3
// baseline (speedup 1.0000x reference)
#include <cuda_runtime.h>
#include <cuda_bf16.h>

// GLRK 4th-order (2-stage Gauss-Legendre) implicit step, B=8192, D=64.
// Picard iteration:  k1 = A1*(y0 + h*(a11 k1 + a12 k2)),
//                    k2 = A2*(y0 + h*(a21 k1 + a22 k2));  7 iters << 1e-3.
//
// R3 changes vs R2 (reg-bound occupancy at 29.8% was starving HBM overlap):
//  - 256 threads/CTA, 2 rows x 16 cols tile (32 tile regs) -> ~60 regs,
//    __launch_bounds__(256,4): 4 CTAs/SM = 50% occupancy.
//  - w vector in 4 chunks padded to 20 floats so the 4 broadcast LDS.128
//    addresses per warp hit disjoint banks.
//  - partial dots reduced over 4 lanes with 2 shfl_xor stages.
//  - streaming cache hints on the A pass-through copy.

#define DD 64
#define NITER 7
#define ROWPAD 68    // A staging row stride (16B aligned)
#define WCH 20       // w chunk stride: 16 data + 4 pad floats (16B aligned)

__global__ void __launch_bounds__(256, 4)
glrk4_kernel(const float* __restrict__ gA1,
             const float* __restrict__ gA2,
             const float* __restrict__ gy0,
             const float* __restrict__ gh,
             float* __restrict__ outY,
             float* __restrict__ outA1,
             float* __restrict__ outA2)
{
    __shared__ __align__(16) float buf1[DD][ROWPAD];
    __shared__ __align__(16) float buf2[DD][ROWPAD];
    __shared__ __align__(16) float y0s[DD];
    __shared__ __align__(16) float w1s[4 * WCH];
    __shared__ __align__(16) float w2s[4 * WCH];
    __shared__ __align__(16) float k1s[DD];
    __shared__ __align__(16) float k2s[DD];

    const int tid = threadIdx.x;
    const size_t b = blockIdx.x;
    const float h = __ldg(gh);

    const float4* g1 = (const float4*)(gA1 + b * (DD * DD));
    const float4* g2 = (const float4*)(gA2 + b * (DD * DD));
    float4* o1 = (float4*)(outA1 + b * (DD * DD));
    float4* o2 = (float4*)(outA2 + b * (DD * DD));

    // Stage A1/A2 into smem (coalesced LDG.128) and emit the output copy.
    // 1024 float4 per matrix, 256 threads -> 4 each.
    #pragma unroll
    for (int i = tid; i < DD * DD / 4; i += 256) {
        const int row = i >> 4;
        const int c   = (i & 15) << 2;
        float4 v1 = __ldcs(&g1[i]);
        *(float4*)&buf1[row][c] = v1;
        __stcs(&o1[i], v1);
        float4 v2 = __ldcs(&g2[i]);
        *(float4*)&buf2[row][c] = v2;
        __stcs(&o2[i], v2);
    }
    if (tid < DD) {
        float yv = gy0[b * DD + tid];
        y0s[tid] = yv;
        const int wi = (tid >> 4) * WCH + (tid & 15);
        w1s[wi] = yv;   // first matvec with w = y0 gives k = R
        w2s[wi] = yv;
    }
    __syncthreads();

    // Thread (q, qt): rows {2q, 2q+1} (q<32 -> A1, else A2), cols [16qt,16qt+16)
    const int q  = tid >> 2;
    const int qt = tid & 3;
    const bool isA1 = (q < 32);
    const int r0 = (isA1 ? q : (q - 32)) << 1;

    float4 ra[4], rb[4];
    {
        const float (*bufp)[ROWPAD] = isA1 ? buf1 : buf2;
        const float4* pa = (const float4*)&bufp[r0][qt << 4];
        const float4* pb = (const float4*)&bufp[r0 + 1][qt << 4];
        #pragma unroll
        for (int m = 0; m < 4; m++) { ra[m] = pa[m]; rb[m] = pb[m]; }
    }

    const float4* ws = (const float4*)((isA1 ? w1s : w2s) + qt * WCH);
    float* ks = isA1 ? k1s : k2s;

    const float cA11 = 0.25f;
    const float cA12 = 0.25f - 0.288675134594812882f;  // 1/4 - sqrt(3)/6
    const float cA21 = 0.25f + 0.288675134594812882f;  // 1/4 + sqrt(3)/6
    const float cA22 = 0.25f;

    #pragma unroll 1
    for (int it = 0; it < NITER; it++) {
        float a0 = 0.f, a1 = 0.f, a2 = 0.f, a3 = 0.f;
        float b0 = 0.f, b1 = 0.f, b2 = 0.f, b3 = 0.f;
        #pragma unroll
        for (int m = 0; m < 4; m++) {
            float4 w = ws[m];              // broadcast, conflict-free
            a0 = fmaf(ra[m].x, w.x, a0);
            a1 = fmaf(ra[m].y, w.y, a1);
            a2 = fmaf(ra[m].z, w.z, a2);
            a3 = fmaf(ra[m].w, w.w, a3);
            b0 = fmaf(rb[m].x, w.x, b0);
            b1 = fmaf(rb[m].y, w.y, b1);
            b2 = fmaf(rb[m].z, w.z, b2);
            b3 = fmaf(rb[m].w, w.w, b3);
        }
        float sa = (a0 + a1) + (a2 + a3);
        float sb = (b0 + b1) + (b2 + b3);
        sa += __shfl_xor_sync(0xffffffffu, sa, 1);
        sa += __shfl_xor_sync(0xffffffffu, sa, 2);
        sb += __shfl_xor_sync(0xffffffffu, sb, 1);
        sb += __shfl_xor_sync(0xffffffffu, sb, 2);
        if (qt == 0) {
            ks[r0]     = sa;
            ks[r0 + 1] = sb;
        }
        __syncthreads();

        if (it < NITER - 1) {
            if (tid < 128) {
                const int j = tid & 63;
                float k1 = k1s[j];
                float k2 = k2s[j];
                float y  = y0s[j];
                const int wi = (j >> 4) * WCH + (j & 15);
                if (tid < 64)
                    w1s[wi] = fmaf(h, fmaf(cA11, k1, cA12 * k2), y);
                else
                    w2s[wi] = fmaf(h, fmaf(cA21, k1, cA22 * k2), y);
            }
            __syncthreads();
        }
    }

    if (tid < DD) {
        // y_next = y0 + h*(0.5*k1 + 0.5*k2)
        outY[b * DD + tid] = fmaf(h, 0.5f * (k1s[tid] + k2s[tid]), y0s[tid]);
    }
}

extern "C" void kernel_launch(void* const* d_in, const int* in_sizes, int n_in,
                              void* d_out, int out_size)
{
    const float* A1 = (const float*)d_in[0];   // [B, 64, 64]
    const float* A2 = (const float*)d_in[1];   // [B, 64, 64]
    const float* y0 = (const float*)d_in[2];   // [B, 64]
    const float* h  = (const float*)d_in[3];   // scalar

    float* out  = (float*)d_out;
    const size_t yElems = (size_t)in_sizes[2];         // B*64
    const size_t aElems = (size_t)in_sizes[0];         // B*64*64
    float* outY  = out;                                 // (B, 64)
    float* outA1 = out + yElems;                        // stack[0] = A1
    float* outA2 = outA1 + aElems;                      // stack[1] = A2

    const int B = (int)(yElems / DD);
    glrk4_kernel<<<B, 256>>>(A1, A2, y0, h, outY, outA1, outA2);
    (void)n_in; (void)out_size;
}

// round 5
// speedup vs baseline: 1.0071x; 1.0071x over previous
#include <cuda_runtime.h>
#include <cuda_bf16.h>

// GLRK 4th-order (2-stage Gauss-Legendre) implicit step, B=8192, D=64.
// Picard iteration:  k1 = A1*(y0 + h*(a11 k1 + a12 k2)),
//                    k2 = A2*(y0 + h*(a21 k1 + a22 k2));  8 iters -> fp32 noise.
//
// R4 vs R2 (95.7us): intra-CTA software pipeline. Each CTA handles NB=4
// batches; cp.async prefetches batch j+1 into the (single) smem buffer while
// batch j's iterations run entirely out of registers. Copy-out of A happens
// straight from tile registers (full 128B lines per lane). This keeps HBM
// demand continuous instead of convoy-phased. R2's thread layout, reduction
// and natural register allocation are preserved (R3 showed forced reg caps
// and cache hints regress).

#define DD 64
#define NITER 8
#define ROWPAD 68   // A staging row stride (16B aligned)
#define WPAD 36     // second w half offset (bank shift, 16B aligned)
#define NB 4        // batches per CTA

__device__ __forceinline__ void cp_async16(void* smem_dst, const void* gmem_src) {
    unsigned sm = (unsigned)__cvta_generic_to_shared(smem_dst);
    asm volatile("cp.async.cg.shared.global [%0], [%1], 16;\n"
                 :: "r"(sm), "l"(gmem_src));
}
__device__ __forceinline__ void cp_commit()   { asm volatile("cp.async.commit_group;\n"); }
__device__ __forceinline__ void cp_wait_all() { asm volatile("cp.async.wait_group 0;\n" ::: "memory"); }

__global__ void __launch_bounds__(128)
glrk4_kernel(const float* __restrict__ gA1,
             const float* __restrict__ gA2,
             const float* __restrict__ gy0,
             const float* __restrict__ gh,
             float* __restrict__ outY,
             float* __restrict__ outA1,
             float* __restrict__ outA2)
{
    __shared__ __align__(16) float buf1[DD][ROWPAD];
    __shared__ __align__(16) float buf2[DD][ROWPAD];
    __shared__ __align__(16) float y0buf[DD];
    __shared__ __align__(16) float y0s[DD];
    __shared__ __align__(16) float w1s[2 * WPAD];
    __shared__ __align__(16) float w2s[2 * WPAD];
    __shared__ __align__(16) float k1s[DD];
    __shared__ __align__(16) float k2s[DD];

    const int tid = threadIdx.x;
    const float h = __ldg(gh);
    const size_t b0 = (size_t)blockIdx.x * NB;

    // Prefetch batch 0 (coalesced 16B cp.async, 512B/warp-instruction).
    {
        const float4* g1 = (const float4*)(gA1 + b0 * (DD * DD));
        const float4* g2 = (const float4*)(gA2 + b0 * (DD * DD));
        #pragma unroll
        for (int t = 0; t < 8; t++) {
            const int i = tid + t * 128;
            const int row = i >> 4;
            const int c   = (i & 15) << 2;
            cp_async16(&buf1[row][c], &g1[i]);
            cp_async16(&buf2[row][c], &g2[i]);
        }
        if (tid < 16) cp_async16(&y0buf[tid * 4], gy0 + b0 * DD + tid * 4);
        cp_commit();
    }

    // Thread (p, hf): rows {2p, 2p+1} (p<32 -> A1 else A2), cols [32hf, 32hf+32)
    const int p  = tid >> 1;
    const int hf = tid & 1;
    const bool isA1 = (p < 32);
    const int r0 = (isA1 ? p : (p - 32)) << 1;
    float* ks = isA1 ? k1s : k2s;
    const float4* ws = (const float4*)((isA1 ? w1s : w2s) + hf * WPAD);

    const float cA11 = 0.25f;
    const float cA12 = 0.25f - 0.288675134594812882f;  // 1/4 - sqrt(3)/6
    const float cA21 = 0.25f + 0.288675134594812882f;  // 1/4 + sqrt(3)/6
    const float cA22 = 0.25f;

    #pragma unroll 1
    for (int j = 0; j < NB; j++) {
        const size_t b = b0 + j;
        cp_wait_all();
        __syncthreads();   // batch data visible; also orders prev-batch reads

        // y0 copy out of the prefetch slot + w init (w = y0 -> first k = R)
        if (tid < DD) {
            float yv = y0buf[tid];
            y0s[tid] = yv;
            const int wi = (tid & 31) + ((tid >> 5) ? WPAD : 0);
            w1s[wi] = yv;
            w2s[wi] = yv;
        }

        // Pull this thread's tile into registers.
        float4 ra[8], rb[8];
        {
            const float (*bufp)[ROWPAD] = isA1 ? buf1 : buf2;
            const float4* pa = (const float4*)&bufp[r0][hf << 5];
            const float4* pb = (const float4*)&bufp[r0 + 1][hf << 5];
            #pragma unroll
            for (int m = 0; m < 8; m++) { ra[m] = pa[m]; rb[m] = pb[m]; }
        }

        // Copy-out A straight from registers (each lane: two full 128B runs).
        {
            float4* o = (float4*)((isA1 ? outA1 : outA2) + b * (DD * DD));
            float4* oa = o + r0 * 16 + (hf << 3);
            float4* ob = o + (r0 + 1) * 16 + (hf << 3);
            #pragma unroll
            for (int m = 0; m < 8; m++) { oa[m] = ra[m]; ob[m] = rb[m]; }
        }
        __syncthreads();   // all buf/y0buf reads done; w-init visible

        // Prefetch next batch into the same buffer; overlaps the iterations.
        if (j + 1 < NB) {
            const size_t bn = b + 1;
            const float4* g1 = (const float4*)(gA1 + bn * (DD * DD));
            const float4* g2 = (const float4*)(gA2 + bn * (DD * DD));
            #pragma unroll
            for (int t = 0; t < 8; t++) {
                const int i = tid + t * 128;
                const int row = i >> 4;
                const int c   = (i & 15) << 2;
                cp_async16(&buf1[row][c], &g1[i]);
                cp_async16(&buf2[row][c], &g2[i]);
            }
            if (tid < 16) cp_async16(&y0buf[tid * 4], gy0 + bn * DD + tid * 4);
            cp_commit();
        }

        // Picard iterations (registers + tiny w/k smem only).
        #pragma unroll 1
        for (int it = 0; it < NITER; it++) {
            float a0 = 0.f, a1 = 0.f, a2 = 0.f, a3 = 0.f;
            float b0_ = 0.f, b1_ = 0.f, b2_ = 0.f, b3_ = 0.f;
            #pragma unroll
            for (int m = 0; m < 8; m++) {
                float4 w = ws[m];          // broadcast LDS.128, conflict-free
                a0 = fmaf(ra[m].x, w.x, a0);
                a1 = fmaf(ra[m].y, w.y, a1);
                a2 = fmaf(ra[m].z, w.z, a2);
                a3 = fmaf(ra[m].w, w.w, a3);
                b0_ = fmaf(rb[m].x, w.x, b0_);
                b1_ = fmaf(rb[m].y, w.y, b1_);
                b2_ = fmaf(rb[m].z, w.z, b2_);
                b3_ = fmaf(rb[m].w, w.w, b3_);
            }
            float sa = (a0 + a1) + (a2 + a3);
            float sb = (b0_ + b1_) + (b2_ + b3_);
            sa += __shfl_xor_sync(0xffffffffu, sa, 1);
            sb += __shfl_xor_sync(0xffffffffu, sb, 1);
            ks[r0 + hf] = hf ? sb : sa;
            __syncthreads();

            if (it < NITER - 1) {
                if (tid < DD) {
                    float k1 = k1s[tid];
                    float k2 = k2s[tid];
                    float y  = y0s[tid];
                    const int wi = (tid & 31) + ((tid >> 5) ? WPAD : 0);
                    w1s[wi] = fmaf(h, fmaf(cA11, k1, cA12 * k2), y);
                    w2s[wi] = fmaf(h, fmaf(cA21, k1, cA22 * k2), y);
                }
                __syncthreads();
            }
        }

        if (tid < DD) {
            // y_next = y0 + h*(0.5*k1 + 0.5*k2)
            outY[b * DD + tid] = fmaf(h, 0.5f * (k1s[tid] + k2s[tid]), y0s[tid]);
        }
        // next loop's wait+__syncthreads orders these reads vs. new writes
    }
}

extern "C" void kernel_launch(void* const* d_in, const int* in_sizes, int n_in,
                              void* d_out, int out_size)
{
    const float* A1 = (const float*)d_in[0];   // [B, 64, 64]
    const float* A2 = (const float*)d_in[1];   // [B, 64, 64]
    const float* y0 = (const float*)d_in[2];   // [B, 64]
    const float* h  = (const float*)d_in[3];   // scalar

    float* out  = (float*)d_out;
    const size_t yElems = (size_t)in_sizes[2];         // B*64
    const size_t aElems = (size_t)in_sizes[0];         // B*64*64
    float* outY  = out;                                 // (B, 64)
    float* outA1 = out + yElems;                        // stack[0] = A1
    float* outA2 = outA1 + aElems;                      // stack[1] = A2

    const int B = (int)(yElems / DD);
    glrk4_kernel<<<B / NB, 128>>>(A1, A2, y0, h, outY, outA1, outA2);
    (void)n_in; (void)out_size;
}